// round 12
// baseline (speedup 1.0000x reference)
#include <cuda_runtime.h>

#define R 16
#define A 8
#define THREADS 256

typedef unsigned long long ull;

// Packed f32x2 ops (Blackwell): register pairs holding (lo, hi) floats.
#define ADD2(o, a, b)     asm("add.rn.f32x2 %0, %1, %2;"     : "=l"(o) : "l"(a), "l"(b))
#define MUL2(o, a, b)     asm("mul.rn.f32x2 %0, %1, %2;"     : "=l"(o) : "l"(a), "l"(b))
#define FMA2(o, a, b, c)  asm("fma.rn.f32x2 %0, %1, %2, %3;" : "=l"(o) : "l"(a), "l"(b), "l"(c))
#define PACK2(o, lo, hi)  asm("mov.b64 %0, {%1, %2};"        : "=l"(o) : "f"(lo), "f"(hi))
#define UNPACK2(lo, hi, i) asm("mov.b64 {%0, %1}, %2;"       : "=f"(lo), "=f"(hi) : "l"(i))

__device__ __forceinline__ float ex2f(float x) {
    float r;
    asm("ex2.approx.f32 %0, %1;" : "=f"(r) : "f"(x));
    return r;
}

__global__ __launch_bounds__(THREADS)   // NO min-blocks cap: let ptxas pick regs, no spills
void t2fls_kernel(const float* __restrict__ x_in,
                  const float* __restrict__ W,
                  const float* __restrict__ c1,
                  const float* __restrict__ c2,
                  float* __restrict__ out, int n)
{
    // d = U-L per (rule, row). Column t is touched only by thread t.
    __shared__ float shD[R][THREADS];                       // 16 KB
    // Coefficients in c1-sorted rule order, packed as pairs (v[a], v[a+4]):
    // float index: slot*8 + (a&3)*2 + (a>>2)  -> ull k of rule j = (v[j][k], v[j][k+4])
    __shared__ __align__(16) ull sh_nm[R][4];   // negated centers
    __shared__ __align__(16) ull sh_gb[R][4];   // -0.5*log2(e)/smax^2  (mu_big / U)
    __shared__ __align__(16) ull sh_gs[R][4];   // -0.5*log2(e)/smin^2  (mu_small / L)
    // Per sorted slot j: (c1s[j], c2s[j], as_float(q[j]*THREADS), c2[p1[j]])
    __shared__ float4 shScan[R];
    __shared__ int   sh_p1[R], sh_inv1[R], sh_p2[R];
    __shared__ float sh_c1s[R], sh_c2s[R];

    int t = threadIdx.x;

    // ---- Phase A: parallel rank-sort of c1 (threads 0..15) and c2 (threads 16..31) ----
    if (t < R) {
        float cj = c1[t];
        int rank = 0;
        #pragma unroll
        for (int i = 0; i < R; i++) {
            float ci = c1[i];
            rank += (ci < cj) || (ci == cj && i < t);   // stable
        }
        sh_p1[rank] = t;
        sh_inv1[t] = rank;
        sh_c1s[rank] = cj;
    } else if (t < 2 * R) {
        int j = t - R;
        float cj = c2[j];
        int rank = 0;
        #pragma unroll
        for (int i = 0; i < R; i++) {
            float ci = c2[i];
            rank += (ci < cj) || (ci == cj && i < j);   // stable
        }
        sh_p2[rank] = j;
        sh_c2s[rank] = cj;
    }
    __syncthreads();

    // ---- Phase B: coefficient transform into c1-sorted, pair-packed layout ----
    if (t < R * A) {
        int r = t >> 3, a = t & 7;
        // offsets = A*r + a == t ; m = W[t], s1 = W[t+1], s2 = W[t+2]
        float m  = W[t];
        float s1 = W[t + 1];
        float s2 = W[t + 2];
        float smax = fmaxf(s1, s2);
        float smin = fminf(s1, s2);
        const float k = -0.5f * 1.44269504088896340736f;  // -0.5 * log2(e)
        int slot = sh_inv1[r];
        int idx = slot * 8 + (a & 3) * 2 + (a >> 2);      // pair p=(a&3), half=(a>>2)
        ((float*)sh_nm)[idx] = -m;
        ((float*)sh_gb)[idx] = k / (smax * smax);
        ((float*)sh_gs)[idx] = k / (smin * smin);
    }
    if (t < R) {
        int q = sh_inv1[sh_p2[t]];   // slot (in c1-order storage) of rule p2[t]
        shScan[t] = make_float4(sh_c1s[t], sh_c2s[t],
                                __int_as_float(q * THREADS),
                                c2[sh_p1[t]]);           // c2 value of rule at c1-slot t
    }
    __syncthreads();

    int i = blockIdx.x * THREADS + t;
    if (i >= n) return;

    // Load the 8-feature row; pack as pairs (x[p], x[p+4]).
    const float4* xp = (const float4*)(x_in + (size_t)i * A);
    float4 a0 = xp[0];
    float4 a1 = xp[1];
    ull x0, x1, x2, x3;
    PACK2(x0, a0.x, a1.x);
    PACK2(x1, a0.y, a1.y);
    PACK2(x2, a0.z, a1.z);
    PACK2(x3, a0.w, a1.w);

    float s0 = 0.f, t0 = 0.f;     // sum(c1*L), sum(L)
    float s0r = 0.f, t0r = 0.f;   // sum(c2*U), sum(U)

    #pragma unroll
    for (int j = 0; j < R; j++) {
        ulonglong2 nm01 = *(const ulonglong2*)&sh_nm[j][0];
        ulonglong2 nm23 = *(const ulonglong2*)&sh_nm[j][2];
        ulonglong2 gb01 = *(const ulonglong2*)&sh_gb[j][0];
        ulonglong2 gb23 = *(const ulonglong2*)&sh_gb[j][2];
        ulonglong2 gs01 = *(const ulonglong2*)&sh_gs[j][0];
        ulonglong2 gs23 = *(const ulonglong2*)&sh_gs[j][2];

        ull acc_b = 0ull, acc_s = 0ull;
        ull d2, e2;
        ADD2(d2, x0, nm01.x); MUL2(e2, d2, d2);
        FMA2(acc_b, e2, gb01.x, acc_b); FMA2(acc_s, e2, gs01.x, acc_s);
        ADD2(d2, x1, nm01.y); MUL2(e2, d2, d2);
        FMA2(acc_b, e2, gb01.y, acc_b); FMA2(acc_s, e2, gs01.y, acc_s);
        ADD2(d2, x2, nm23.x); MUL2(e2, d2, d2);
        FMA2(acc_b, e2, gb23.x, acc_b); FMA2(acc_s, e2, gs23.x, acc_s);
        ADD2(d2, x3, nm23.y); MUL2(e2, d2, d2);
        FMA2(acc_b, e2, gb23.y, acc_b); FMA2(acc_s, e2, gs23.y, acc_s);

        float bl, bh, ql, qh;
        UNPACK2(bl, bh, acc_b);
        UNPACK2(ql, qh, acc_s);
        float U = ex2f(bl + bh);   // prod_a mu_big  = exp2(sum of scaled exponents)
        float L = ex2f(ql + qh);   // prod_a mu_small

        float4 sc = shScan[j];
        s0  = fmaf(sc.x, L, s0);   t0  += L;    // sc.x = c1 of this (sorted) rule
        s0r = fmaf(sc.w, U, s0r);  t0r += U;    // sc.w = c2 of this rule
        shD[j][t] = U - L;
    }

    float left  = __fdividef(s0,  t0);
    float right = __fdividef(s0r, t0r);

    float cs = 0.f, ct = 0.f, csr = 0.f, ctr = 0.f;
    const float* shDf = &shD[0][0];
    #pragma unroll
    for (int j = 0; j < R; j++) {
        float4 sc = shScan[j];
        // Left scan: storage is already c1-sorted -> compile-time offsets.
        float dj = shD[j][t];
        cs = fmaf(sc.x, dj, cs);
        ct += dj;
        left = fminf(left, __fdividef(s0 + cs, t0 + ct));
        // Right scan: c2-sorted order via runtime slot offset (same-thread column).
        int off = __float_as_int(sc.z);
        float dq = shDf[off + t];           // = U - L of rule p2[j]
        csr = fmaf(sc.y, dq, csr);          // accumulates sum c2s*(U-L)
        ctr += dq;
        // dr = L - U = -dq  =>  ratio = (s0r - csr)/(t0r - ctr)
        right = fmaxf(right, __fdividef(s0r - csr, t0r - ctr));
    }

    out[i] = 0.5f * (left + right);
}

extern "C" void kernel_launch(void* const* d_in, const int* in_sizes, int n_in,
                              void* d_out, int out_size) {
    const float* x  = (const float*)d_in[0];
    const float* W  = (const float*)d_in[1];
    const float* c1 = (const float*)d_in[2];
    const float* c2 = (const float*)d_in[3];
    float* out = (float*)d_out;
    int n = out_size;  // one output per row

    int blocks = (n + THREADS - 1) / THREADS;
    t2fls_kernel<<<blocks, THREADS>>>(x, W, c1, c2, out, n);
}